// round 11
// baseline (speedup 1.0000x reference)
#include <cuda_runtime.h>
#include <cuda_bf16.h>
#include <cstdint>
#include <math.h>

#define EPSR 1e-6f

// ---------------- smem float offsets (total 56576 floats = 226304 B) --------
#define OFF_SHI 0          // Shi bf16 [208 m][216 k] = 44928 bf16 = 22464 f
#define OFF_SLO 22464      // Slo bf16 [208][216]                  -> 44928
#define OFF_AH  44928      // phase1: A-chunk hi bf16 [208][56] = 5824 f
#define OFF_AL  50752      //         A-chunk lo                  -> 56576
// phase-2 smalls alias the AH/AL region (dead after phase 1):
#define P2_Q    44928      // Q fp32 [196][4] = 784
#define P2_P    45712      // P fp32 [196][4] = 784
#define P2_PTH  46496      // Pt hi bf16 [8 n][216 k] = 1728 bf16 = 864 f
#define P2_PTL  47360      // Pt lo                                -> 48224
#define P2_B    48224
#define P2_C    48280
#define P2_BTB  48336
#define P2_CTC  48352
#define P2_ATA  48368
#define P2_GI   48384
#define P2_M    48400      // 56 -> 48456
#define P2_PT32 48456      // fp32 P^T [4][196] for phase 3 -> 49240
// phase-3 smalls (Tc4 staging aliases Shi region at 0):
#define P3_SY2  49240
#define P3_RED  49752
#define P3_SZ   50264
#define P3_SW1  50296
#define P3_SW2  50312
#define P3_GATE 50316      // -> 50828
#define SMEM_FLOATS 56576

#define SPITCH 216         // bf16 cols per S row (432 B; 108w -> 12l mod 32 distinct)
#define APITCH 56          // bf16 cols per A row (112 B; proven round 7/8)

__device__ __forceinline__ uint32_t smem_u32(const void* p) {
    uint32_t a;
    asm("{ .reg .u64 t; cvta.to.shared.u64 t, %1; cvt.u32.u64 %0, t; }" : "=r"(a) : "l"(p));
    return a;
}

// Warp-parallel 4x4 SPD inverse via adjugate (lanes 0..15)
__device__ __forceinline__ void inv4_warp16(const float* __restrict__ ga,
                                            const float* __restrict__ gb,
                                            float* __restrict__ gi, int t)
{
    float G[16];
#pragma unroll
    for (int e = 0; e < 16; e++)
        G[e] = ga[e] * gb[e] + ((e % 5 == 0) ? EPSR : 0.f);
    int i = t >> 2, j = t & 3;
    int r0 = (i == 0) ? 1 : 0, r1 = (i < 2) ? 2 : 1, r2 = (i < 3) ? 3 : 2;
    int c0 = (j == 0) ? 1 : 0, c1 = (j < 2) ? 2 : 1, c2 = (j < 3) ? 3 : 2;
    float a = G[r0 * 4 + c0], bb = G[r0 * 4 + c1], c = G[r0 * 4 + c2];
    float d = G[r1 * 4 + c0], e  = G[r1 * 4 + c1], f = G[r1 * 4 + c2];
    float g = G[r2 * 4 + c0], h  = G[r2 * 4 + c1], i2 = G[r2 * 4 + c2];
    float det3 = a * (e * i2 - f * h) - bb * (d * i2 - f * g) + c * (d * h - e * g);
    float cof = ((i + j) & 1) ? -det3 : det3;
    const unsigned m16 = 0x0000ffffu;
    float c0v = __shfl_sync(m16, cof, 0);
    float c1v = __shfl_sync(m16, cof, 1);
    float c2v = __shfl_sync(m16, cof, 2);
    float c3v = __shfl_sync(m16, cof, 3);
    float det = G[0] * c0v + G[1] * c1v + G[2] * c2v + G[3] * c3v;
    float cji = __shfl_sync(m16, cof, j * 4 + i);
    gi[t] = cji / det;
}

#define MMA_BF16(D, A, B)                                                         \
    asm volatile("mma.sync.aligned.m16n8k16.row.col.f32.bf16.bf16.f32 "           \
        "{%0,%1,%2,%3}, {%4,%5,%6,%7}, {%8,%9}, {%0,%1,%2,%3};"                   \
        : "+f"((D)[0]), "+f"((D)[1]), "+f"((D)[2]), "+f"((D)[3])                  \
        : "r"((A)[0]), "r"((A)[1]), "r"((A)[2]), "r"((A)[3]),                     \
          "r"((B)[0]), "r"((B)[1]))

#define LDM_X4(R, ADDR)                                                           \
    asm volatile("ldmatrix.sync.aligned.m8n8.x4.shared.b16 {%0,%1,%2,%3}, [%4];"  \
        : "=r"((R)[0]), "=r"((R)[1]), "=r"((R)[2]), "=r"((R)[3]) : "r"(ADDR))

#define LDM_X2(R, ADDR)                                                           \
    asm volatile("ldmatrix.sync.aligned.m8n8.x2.shared.b16 {%0,%1}, [%2];"        \
        : "=r"((R)[0]), "=r"((R)[1]) : "r"(ADDR))

extern __shared__ float sm[];

__device__ __forceinline__ void bf16_split(float v, __nv_bfloat16& h, __nv_bfloat16& l) {
    h = __float2bfloat16(v);
    l = __float2bfloat16(v - __bfloat162float(h));
}

// One pass of the Gram build: n-tiles [NI0, NI0+NT). Warp wid<13 owns m-strip wid.
// Loads x, converts in registers to bf16 hi/lo A-chunk [196+pad][32ch], does MMA,
// then splits fp32 accumulators into Shi/Slo bf16.
template<int NI0, int NT>
__device__ __forceinline__ void gram_pass(const float* __restrict__ xs,
                                          int t, int wid, int lane,
                                          uint32_t ah_u32, uint32_t al_u32)
{
    float acc[NT][4];
#pragma unroll
    for (int i = 0; i < NT; i++) {
        acc[i][0] = 0.f; acc[i][1] = 0.f; acc[i][2] = 0.f; acc[i][3] = 0.f;
    }
    __nv_bfloat16* AH = (__nv_bfloat16*)(sm + OFF_AH);
    __nv_bfloat16* AL = (__nv_bfloat16*)(sm + OFF_AL);
    const int mi = wid;

    for (int ch = 0; ch < 16; ++ch) {
        // load 32 channels x 196 floats, convert in regs, store transposed bf16
        {
            const float4* src = (const float4*)(xs + ch * 32 * 196);
            for (int v = t; v < 1568; v += 512) {
                int c = v / 49, i4 = v - 49 * c;
                float4 xv = src[v];
                int base = (i4 * 4) * APITCH + c;
                __nv_bfloat16 h, l;
                bf16_split(xv.x, h, l); AH[base] = h;              AL[base] = l;
                bf16_split(xv.y, h, l); AH[base + APITCH] = h;     AL[base + APITCH] = l;
                bf16_split(xv.z, h, l); AH[base + 2 * APITCH] = h; AL[base + 2 * APITCH] = l;
                bf16_split(xv.w, h, l); AH[base + 3 * APITCH] = h; AL[base + 3 * APITCH] = l;
            }
        }
        __syncthreads();
        if (wid < 13) {
#pragma unroll
            for (int k16 = 0; k16 < 2; ++k16) {
                const int kof = k16 * 16;
                uint32_t aoff = (uint32_t)((mi * 16 + (lane & 15)) * 112 +
                                           (kof + ((lane >> 4) << 3)) * 2);
                uint32_t ah[4], al[4];
                LDM_X4(ah, ah_u32 + aoff);
                LDM_X4(al, al_u32 + aoff);
                uint32_t boff = (uint32_t)((lane & 7) * 112 + (kof + (lane & 8)) * 2);
#pragma unroll
                for (int nt = 0; nt < NT; ++nt) {
                    uint32_t bo = boff + (uint32_t)((NI0 + nt) * 8 * 112);
                    uint32_t bh[2], bl[2];
                    LDM_X2(bh, ah_u32 + bo);
                    LDM_X2(bl, al_u32 + bo);
                    MMA_BF16(acc[nt], ah, bh);
                    MMA_BF16(acc[nt], ah, bl);
                    MMA_BF16(acc[nt], al, bh);
                }
            }
        }
        __syncthreads();
    }
    // epilogue: split accumulators to Shi/Slo bf16 (guarded; pads stay zero)
    if (wid < 13) {
        __nv_bfloat16* SH = (__nv_bfloat16*)(sm + OFF_SHI);
        __nv_bfloat16* SL = (__nv_bfloat16*)(sm + OFF_SLO);
        int r0 = mi * 16 + (lane >> 2);
        int r1 = r0 + 8;
#pragma unroll
        for (int nt = 0; nt < NT; ++nt) {
            int cn = (NI0 + nt) * 8 + (lane & 3) * 2;
#pragma unroll
            for (int e = 0; e < 4; ++e) {
                int r = (e < 2) ? r0 : r1;
                int c = cn + (e & 1);
                if (r < 196 && c < 196) {
                    __nv_bfloat16 h, l;
                    bf16_split(acc[nt][e], h, l);
                    SH[r * SPITCH + c] = h;
                    SL[r * SPITCH + c] = l;
                }
            }
        }
    }
}

__global__ void __launch_bounds__(512, 1)
dese_fused(const float* __restrict__ x, const float* __restrict__ B0,
           const float* __restrict__ C0, const float* __restrict__ w1,
           const float* __restrict__ w2, const float* __restrict__ fw1,
           const float* __restrict__ fw2, float* __restrict__ out)
{
    const int b = blockIdx.x;
    const int t = threadIdx.x;
    const int wid = t >> 5, lane = t & 31;
    const float* xs = x + (size_t)b * 100352;   // T0: [512][196]

    const uint32_t ah_u32 = smem_u32(sm + OFF_AH);
    const uint32_t al_u32 = smem_u32(sm + OFF_AL);
    const uint32_t shi_u32 = smem_u32(sm + OFF_SHI);
    const uint32_t slo_u32 = smem_u32(sm + OFF_SLO);

    // ---------- one-time zero fills ----------
    {
        __nv_bfloat16* AH = (__nv_bfloat16*)(sm + OFF_AH);
        __nv_bfloat16* AL = (__nv_bfloat16*)(sm + OFF_AL);
        __nv_bfloat16* SH = (__nv_bfloat16*)(sm + OFF_SHI);
        __nv_bfloat16* SL = (__nv_bfloat16*)(sm + OFF_SLO);
        __nv_bfloat16 z = __float2bfloat16(0.f);
        // A pad rows 196..207 (672 elements)
        for (int v = t; v < 672; v += 512) { AH[196 * APITCH + v] = z; AL[196 * APITCH + v] = z; }
        // S pads: rows 196..207 (12*216) + cols 196..215 of rows 0..195 (196*20)
        for (int v = t; v < 6512; v += 512) {
            int r, c;
            if (v < 2592) { r = 196 + v / 216; c = v - 216 * (v / 216); }
            else { int u = v - 2592; r = u / 20; c = 196 + (u - 20 * (u / 20)); }
            SH[r * SPITCH + c] = z;
            SL[r * SPITCH + c] = z;
        }
    }
    __syncthreads();

    // ================= Phase 1: S = T0^T T0 via mma.sync -> Shi/Slo ==========
    gram_pass<0, 13>(xs, t, wid, lane, ah_u32, al_u32);
    gram_pass<13, 12>(xs, t, wid, lane, ah_u32, al_u32);
    __syncthreads();

    // ================= Phase 2: 20 ALS iterations (Q via mma on bf16 S) ======
    {
        float* Q = sm + P2_Q;
        float* sP = sm + P2_P;
        __nv_bfloat16* PTH = (__nv_bfloat16*)(sm + P2_PTH);
        __nv_bfloat16* PTL = (__nv_bfloat16*)(sm + P2_PTL);
        const uint32_t pth_u32 = smem_u32(sm + P2_PTH);
        const uint32_t ptl_u32 = smem_u32(sm + P2_PTL);
        float* sB = sm + P2_B;
        float* sC = sm + P2_C;
        float* sBtB = sm + P2_BTB;
        float* sCtC = sm + P2_CTC;
        float* sAtA = sm + P2_ATA;
        float* sGi = sm + P2_GI;
        float* sM = sm + P2_M;

        // init: factors + zero Pt (rows 4..7 and k-pads stay zero forever)
        if (t >= 400 && t < 456) sB[t - 400] = B0[b * 56 + (t - 400)];
        else if (t >= 456 && t < 512) sC[t - 456] = C0[b * 56 + (t - 456)];
        {
            __nv_bfloat16 z = __float2bfloat16(0.f);
            for (int v = t; v < 1728; v += 512) { PTH[v] = z; PTL[v] = z; }
        }
        __syncthreads();

        for (int it = 0; it < 20; it++) {
            // grams + inverse (warp 0)
            if (t < 32) {
                int which = t >> 4, e = t & 15, a = e >> 2, c2 = e & 3;
                const float* F = which ? sC : sB;
                float s = 0.f;
#pragma unroll
                for (int j = 0; j < 14; j++) s += F[j * 4 + a] * F[j * 4 + c2];
                (which ? sCtC : sBtB)[e] = s;
                __syncwarp();
                if (t < 16) inv4_warp16(sBtB, sCtC, sGi, t);
            }
            __syncthreads();
            // P = KR(B,C) @ Ginv ; also write Pt bf16 hi/lo [n][k]
            if (t < 196) {
                int j = t / 14, k = t - (t / 14) * 14;
                float kr0 = sB[j * 4 + 0] * sC[k * 4 + 0];
                float kr1 = sB[j * 4 + 1] * sC[k * 4 + 1];
                float kr2 = sB[j * 4 + 2] * sC[k * 4 + 2];
                float kr3 = sB[j * 4 + 3] * sC[k * 4 + 3];
#pragma unroll
                for (int r = 0; r < 4; r++) {
                    float pv = kr0 * sGi[0 * 4 + r] + kr1 * sGi[1 * 4 + r] +
                               kr2 * sGi[2 * 4 + r] + kr3 * sGi[3 * 4 + r];
                    sP[t * 4 + r] = pv;
                    __nv_bfloat16 h, l;
                    bf16_split(pv, h, l);
                    PTH[r * SPITCH + t] = h;
                    PTL[r * SPITCH + t] = l;
                }
            }
            __syncthreads();
            if (it == 19) break;            // final A needs only P

            // Q = S @ P via mma: warp wid<13 owns m-strip wid (16 rows)
            if (wid < 13) {
                float qa[4] = {0.f, 0.f, 0.f, 0.f};
#pragma unroll
                for (int kt = 0; kt < 13; ++kt) {
                    const int kof = kt * 16;
                    uint32_t aoff = (uint32_t)((wid * 16 + (lane & 15)) * 432 +
                                               (kof + ((lane >> 4) << 3)) * 2);
                    uint32_t ah[4], al[4];
                    LDM_X4(ah, shi_u32 + aoff);
                    LDM_X4(al, slo_u32 + aoff);
                    uint32_t boff = (uint32_t)((lane & 7) * 432 + (kof + (lane & 8)) * 2);
                    uint32_t bh[2], bl[2];
                    LDM_X2(bh, pth_u32 + boff);
                    LDM_X2(bl, ptl_u32 + boff);
                    MMA_BF16(qa, ah, bh);
                    MMA_BF16(qa, ah, bl);
                    MMA_BF16(qa, al, bh);
                }
                int col = (lane & 3) * 2;
                if (col < 4) {
                    int r0 = wid * 16 + (lane >> 2);
                    if (r0 < 196) *(float2*)(Q + r0 * 4 + col) = make_float2(qa[0], qa[1]);
                    int r1 = r0 + 8;
                    if (r1 < 196) *(float2*)(Q + r1 * 4 + col) = make_float2(qa[2], qa[3]);
                }
            }
            __syncthreads();
            // AtA partials (224 thr) ; M1 (56 thr)
            if (t < 224) {
                int e = t / 14, c = t - (t / 14) * 14;
                int s_ = e >> 2, r = e & 3;
                float v = 0.f;
                int pb = c * 14;
#pragma unroll
                for (int p = 0; p < 14; p++) v += sP[(pb + p) * 4 + s_] * Q[(pb + p) * 4 + r];
                // store partials in sM-adjacent scratch: reuse Q rows? use PT32 region
                (sm + P2_PT32)[e * 14 + c] = v;
            } else if (t >= 256 && t < 312) {
                int e = t - 256; int j = e >> 2, r = e & 3;
                float v = 0.f;
#pragma unroll
                for (int k = 0; k < 14; k++) v += sC[k * 4 + r] * Q[(j * 14 + k) * 4 + r];
                sM[e] = v;
            }
            __syncthreads();
            if (t < 32) {
                if (t < 16) {
                    float v = 0.f;
                    const float* redA = sm + P2_PT32;
#pragma unroll
                    for (int c = 0; c < 14; c++) v += redA[t * 14 + c];
                    sAtA[t] = v;
                }
                __syncwarp();
                if (t < 16) inv4_warp16(sAtA, sCtC, sGi, t);
            }
            __syncthreads();
            if (t < 56) {
                int j = t >> 2, r = t & 3;
                sB[t] = sM[j * 4 + 0] * sGi[0 * 4 + r] + sM[j * 4 + 1] * sGi[1 * 4 + r] +
                        sM[j * 4 + 2] * sGi[2 * 4 + r] + sM[j * 4 + 3] * sGi[3 * 4 + r];
            }
            __syncthreads();
            if (t < 32) {
                if (t < 16) {
                    int a = t >> 2, c2 = t & 3;
                    float s = 0.f;
#pragma unroll
                    for (int j = 0; j < 14; j++) s += sB[j * 4 + a] * sB[j * 4 + c2];
                    sBtB[t] = s;
                }
                __syncwarp();
                if (t < 16) inv4_warp16(sAtA, sBtB, sGi, t);
            } else if (t >= 64 && t < 120) {
                int e = t - 64; int k = e >> 2, r = e & 3;
                float v = 0.f;
#pragma unroll
                for (int j = 0; j < 14; j++) v += sB[j * 4 + r] * Q[(j * 14 + k) * 4 + r];
                sM[e] = v;
            }
            __syncthreads();
            if (t < 56) {
                int k = t >> 2, r = t & 3;
                sC[t] = sM[k * 4 + 0] * sGi[0 * 4 + r] + sM[k * 4 + 1] * sGi[1 * 4 + r] +
                        sM[k * 4 + 2] * sGi[2 * 4 + r] + sM[k * 4 + 3] * sGi[3 * 4 + r];
            }
            __syncthreads();
        }
        // fp32 P^T for phase 3
        __syncthreads();
        if (t < 196) {
            float* Pt32 = sm + P2_PT32;
#pragma unroll
            for (int r = 0; r < 4; r++) Pt32[r * 196 + t] = sP[t * 4 + r];
        }
    }
    __syncthreads();

    // ================= Phase 3: A = T0@Pt, rank_fc, SE gate, apply ==========
    {
        float4* Tc4 = (float4*)sm;              // [64][50] float4 (aliases Shi, dead)
        float* Pt = sm + P2_PT32;
        float* sy2 = sm + P3_SY2;
        float* red = sm + P3_RED;
        float* sz = sm + P3_SZ;
        float* sw1 = sm + P3_SW1;
        float* sw2 = sm + P3_SW2;
        float* sg = sm + P3_GATE;

        if (t >= 448 && t < 464) sw1[t - 448] = w1[t - 448];
        else if (t >= 464 && t < 468) sw2[t - 464] = w2[t - 464];

        const int cl = t >> 3;
        const int s = t & 7;
        __syncthreads();

        for (int ch = 0; ch < 8; ch++) {
            for (int v = t; v < 3200; v += 512) {
                int i = v / 50, c4 = v - 50 * (v / 50);
                if (c4 < 49)
                    Tc4[i * 50 + c4] = *(const float4*)(xs + ch * 12544 + i * 196 + c4 * 4);
            }
            __syncthreads();
            float a0 = 0, a1 = 0, a2 = 0, a3 = 0;
            if (s < 7) {
                const float* row = sm + cl * 200;
#pragma unroll
                for (int j = 0; j < 7; j++) {
                    int q = s * 28 + j * 4;
                    float4 xv = *(const float4*)(row + q);
                    float4 p0 = *(const float4*)(Pt + q);
                    float4 p1 = *(const float4*)(Pt + 196 + q);
                    float4 p2 = *(const float4*)(Pt + 392 + q);
                    float4 p3 = *(const float4*)(Pt + 588 + q);
                    a0 += xv.x * p0.x + xv.y * p0.y + xv.z * p0.z + xv.w * p0.w;
                    a1 += xv.x * p1.x + xv.y * p1.y + xv.z * p1.z + xv.w * p1.w;
                    a2 += xv.x * p2.x + xv.y * p2.y + xv.z * p2.z + xv.w * p2.w;
                    a3 += xv.x * p3.x + xv.y * p3.y + xv.z * p3.z + xv.w * p3.w;
                }
            }
#pragma unroll
            for (int m = 4; m; m >>= 1) {
                a0 += __shfl_xor_sync(0xffffffffu, a0, m);
                a1 += __shfl_xor_sync(0xffffffffu, a1, m);
                a2 += __shfl_xor_sync(0xffffffffu, a2, m);
                a3 += __shfl_xor_sync(0xffffffffu, a3, m);
            }
            if (s == 0) {
                float y2 = 0.f;
#pragma unroll
                for (int s_ = 0; s_ < 4; s_++) {
                    float u = a0 * sw1[s_ * 4 + 0] + a1 * sw1[s_ * 4 + 1] +
                              a2 * sw1[s_ * 4 + 2] + a3 * sw1[s_ * 4 + 3];
                    u = fmaxf(u, 0.f);
                    y2 += u * sw2[s_];
                }
                sy2[ch * 64 + cl] = y2;
            }
            __syncthreads();
        }
        {
            int m = t >> 4, c = t & 15;
            const float* fr = fw1 + m * 512 + c * 32;
            const float* yy = sy2 + c * 32;
            float v = 0.f;
#pragma unroll
            for (int i2 = 0; i2 < 32; i2++) v += fr[i2] * yy[i2];
            red[m * 16 + c] = v;
        }
        __syncthreads();
        if (t < 32) {
            float v = 0.f;
#pragma unroll
            for (int c = 0; c < 16; c++) v += red[t * 16 + c];
            sz[t] = fmaxf(v, 0.f);
        }
        __syncthreads();
        {
            const float* fr = fw2 + t * 32;
            float v = 0.f;
#pragma unroll
            for (int m = 0; m < 32; m++) v += fr[m] * sz[m];
            sg[t] = 1.f / (1.f + expf(-v));
        }
        __syncthreads();
        {
            const float4* xin4 = (const float4*)xs;
            float4* out4 = (float4*)(out + (size_t)b * 100352);
            for (int c = wid; c < 512; c += 16) {
                float g = sg[c];
                const float4* xr = xin4 + c * 49;
                float4* orow = out4 + c * 49;
                float4 xv = xr[lane];
                if (lane < 17) {
                    float4 xv2 = xr[lane + 32];
                    orow[lane + 32] = make_float4(xv2.x * g, xv2.y * g, xv2.z * g, xv2.w * g);
                }
                orow[lane] = make_float4(xv.x * g, xv.y * g, xv.z * g, xv.w * g);
            }
        }
    }
}

extern "C" void kernel_launch(void* const* d_in, const int* in_sizes, int n_in,
                              void* d_out, int out_size) {
    const float* x   = (const float*)d_in[0];
    // d_in[1] = A0: unused (A is overwritten before first use in the reference)
    const float* B0  = (const float*)d_in[2];
    const float* C0  = (const float*)d_in[3];
    const float* w1  = (const float*)d_in[4];
    const float* w2  = (const float*)d_in[5];
    const float* fw1 = (const float*)d_in[6];
    const float* fw2 = (const float*)d_in[7];
    float* out = (float*)d_out;

    int b = in_sizes[0] / 100352;                        // 256
    size_t smem = (size_t)SMEM_FLOATS * sizeof(float);   // 226304 B
    static int configured = 0;
    if (!configured) {
        cudaFuncSetAttribute(dese_fused, cudaFuncAttributeMaxDynamicSharedMemorySize, (int)smem);
        configured = 1;
    }
    dese_fused<<<b, 512, smem>>>(x, B0, C0, w1, w2, fw1, fw2, out);
}

// round 12
// speedup vs baseline: 1.4161x; 1.4161x over previous
#include <cuda_runtime.h>
#include <cuda_bf16.h>
#include <cstdint>
#include <math.h>

#define EPSR 1e-6f
#define NSAMP 256

// ---------------- global scratch (static; no allocation) ----------
// S in float4-panel layout: panel g (g<49) holds cols 4g..4g+3 for all 196 rows:
//   addr(p, 4g+j) = g*784 + p*4 + j   (lane-consecutive p -> coalesced f4 reads)
__device__ float g_Sc[NSAMP * 49 * 784];     // 38416 f/sample = 39.3 MB
__device__ float g_P[NSAMP * 196 * 4];       // final projection (A = T0 @ P)
__device__ float g_gate[NSAMP * 512];        // per-channel sigmoid gate

__device__ __forceinline__ uint32_t smem_u32(const void* p) {
    uint32_t a;
    asm("{ .reg .u64 t; cvta.to.shared.u64 t, %1; cvt.u32.u64 %0, t; }" : "=r"(a) : "l"(p));
    return a;
}

// Warp-parallel 4x4 SPD inverse via adjugate (lanes 0..15)
__device__ __forceinline__ void inv4_warp16(const float* __restrict__ ga,
                                            const float* __restrict__ gb,
                                            float* __restrict__ gi, int t)
{
    float G[16];
#pragma unroll
    for (int e = 0; e < 16; e++)
        G[e] = ga[e] * gb[e] + ((e % 5 == 0) ? EPSR : 0.f);
    int i = t >> 2, j = t & 3;
    int r0 = (i == 0) ? 1 : 0, r1 = (i < 2) ? 2 : 1, r2 = (i < 3) ? 3 : 2;
    int c0 = (j == 0) ? 1 : 0, c1 = (j < 2) ? 2 : 1, c2 = (j < 3) ? 3 : 2;
    float a = G[r0 * 4 + c0], bb = G[r0 * 4 + c1], c = G[r0 * 4 + c2];
    float d = G[r1 * 4 + c0], e  = G[r1 * 4 + c1], f = G[r1 * 4 + c2];
    float g = G[r2 * 4 + c0], h  = G[r2 * 4 + c1], i2 = G[r2 * 4 + c2];
    float det3 = a * (e * i2 - f * h) - bb * (d * i2 - f * g) + c * (d * h - e * g);
    float cof = ((i + j) & 1) ? -det3 : det3;
    const unsigned m16 = 0x0000ffffu;
    float c0v = __shfl_sync(m16, cof, 0);
    float c1v = __shfl_sync(m16, cof, 1);
    float c2v = __shfl_sync(m16, cof, 2);
    float c3v = __shfl_sync(m16, cof, 3);
    float det = G[0] * c0v + G[1] * c1v + G[2] * c2v + G[3] * c3v;
    float cji = __shfl_sync(m16, cof, j * 4 + i);
    gi[t] = cji / det;
}

#define MMA_BF16(D, A, B)                                                         \
    asm volatile("mma.sync.aligned.m16n8k16.row.col.f32.bf16.bf16.f32 "           \
        "{%0,%1,%2,%3}, {%4,%5,%6,%7}, {%8,%9}, {%0,%1,%2,%3};"                   \
        : "+f"((D)[0]), "+f"((D)[1]), "+f"((D)[2]), "+f"((D)[3])                  \
        : "r"((A)[0]), "r"((A)[1]), "r"((A)[2]), "r"((A)[3]),                     \
          "r"((B)[0]), "r"((B)[1]))

#define LDM_X4(R, ADDR)                                                           \
    asm volatile("ldmatrix.sync.aligned.m8n8.x4.shared.b16 {%0,%1,%2,%3}, [%4];"  \
        : "=r"((R)[0]), "=r"((R)[1]), "=r"((R)[2]), "=r"((R)[3]) : "r"(ADDR))

#define LDM_X2(R, ADDR)                                                           \
    asm volatile("ldmatrix.sync.aligned.m8n8.x2.shared.b16 {%0,%1}, [%2];"        \
        : "=r"((R)[0]), "=r"((R)[1]) : "r"(ADDR))

// =====================================================================
// K1: S = T0^T T0 via mma.sync (bf16 two-term split).
// Grid 2*NSAMP: CTA (b, half) computes n-tiles [0,13) or [13,25).
// 2 CTAs/SM.  Panels written straight from accumulators to g_Sc.
// =====================================================================
#define K1_STG  0
#define K1_AHI  6472
#define K1_ALO  12296
#define K1_FLOATS 18120       // 72480 B (2 CTAs/SM: 145 KB < 227 KB)

extern __shared__ float sm[];

template<int NI0, int NT>
__device__ __forceinline__ void gram_pass(const float* __restrict__ xs,
                                          float* __restrict__ gS,
                                          int t, int wid, int lane,
                                          uint32_t ahi_u32, uint32_t alo_u32)
{
    float acc[NT][4];
#pragma unroll
    for (int i = 0; i < NT; i++) {
        acc[i][0] = 0.f; acc[i][1] = 0.f; acc[i][2] = 0.f; acc[i][3] = 0.f;
    }
    float* stgT = sm + K1_STG;
    __nv_bfloat16* AH = (__nv_bfloat16*)(sm + K1_AHI);
    __nv_bfloat16* AL = (__nv_bfloat16*)(sm + K1_ALO);
    const int mi = wid;

    for (int ch = 0; ch < 16; ++ch) {
        // stage 32 channels x 196 floats TRANSPOSED: stg_T[i][c], pitch 33
        {
            const float4* src = (const float4*)(xs + ch * 32 * 196);
            for (int v = t; v < 1568; v += 512) {
                int c = v / 49, i4 = v - 49 * c;
                float4 xv = src[v];
                float* d = stgT + (i4 * 4) * 33 + c;
                d[0]  = xv.x;
                d[33] = xv.y;
                d[66] = xv.z;
                d[99] = xv.w;
            }
        }
        __syncthreads();
        // convert to bf16 hi/lo: conflict-free row reads, contiguous stores
        for (int r = wid; r < 196; r += 16) {
            float v0 = stgT[r * 33 + lane];
            __nv_bfloat16 h = __float2bfloat16(v0);
            float hf = __bfloat162float(h);
            __nv_bfloat16 l = __float2bfloat16(v0 - hf);
            AH[r * 56 + lane] = h;
            AL[r * 56 + lane] = l;
        }
        __syncthreads();
        if (wid < 13) {
#pragma unroll
            for (int k16 = 0; k16 < 2; ++k16) {
                const int kof = k16 * 16;
                uint32_t aoff = (uint32_t)((mi * 16 + (lane & 15)) * 112 +
                                           (kof + ((lane >> 4) << 3)) * 2);
                uint32_t ah[4], al[4];
                LDM_X4(ah, ahi_u32 + aoff);
                LDM_X4(al, alo_u32 + aoff);
                uint32_t boff = (uint32_t)((lane & 7) * 112 + (kof + (lane & 8)) * 2);
#pragma unroll
                for (int nt = 0; nt < NT; ++nt) {
                    uint32_t bo = boff + (uint32_t)((NI0 + nt) * 8 * 112);
                    uint32_t bh[2], bl[2];
                    LDM_X2(bh, ahi_u32 + bo);
                    LDM_X2(bl, alo_u32 + bo);
                    MMA_BF16(acc[nt], ah, bh);
                    MMA_BF16(acc[nt], ah, bl);
                    MMA_BF16(acc[nt], al, bh);
                }
            }
        }
        __syncthreads();
    }
    // epilogue: registers -> g_Sc panels (float2 stores, 8B aligned)
    if (wid < 13) {
        int r0 = mi * 16 + (lane >> 2);
        int r1 = r0 + 8;
#pragma unroll
        for (int nt = 0; nt < NT; ++nt) {
            int cn = (NI0 + nt) * 8 + (lane & 3) * 2;   // even, < 200
            if (cn < 196) {
                int base = (cn >> 2) * 784 + (cn & 3);
                if (r0 < 196) *(float2*)(gS + base + r0 * 4) = make_float2(acc[nt][0], acc[nt][1]);
                if (r1 < 196) *(float2*)(gS + base + r1 * 4) = make_float2(acc[nt][2], acc[nt][3]);
            }
        }
    }
}

__global__ void __launch_bounds__(512, 2)
k1_gram(const float* __restrict__ x)
{
    const int b = blockIdx.x >> 1;
    const int half = blockIdx.x & 1;
    const int t = threadIdx.x;
    const int wid = t >> 5, lane = t & 31;
    const float* xs = x + (size_t)b * 100352;
    float* gS = g_Sc + (size_t)b * 38416;

    const uint32_t ahi_u32 = smem_u32(sm + K1_AHI);
    const uint32_t alo_u32 = smem_u32(sm + K1_ALO);

    // zero pad rows 196..207 (cols 0..31) of AHI/ALO
    {
        __nv_bfloat16* AH = (__nv_bfloat16*)(sm + K1_AHI);
        __nv_bfloat16* AL = (__nv_bfloat16*)(sm + K1_ALO);
        __nv_bfloat16 z = __float2bfloat16(0.f);
        if (t < 384) {
            int r = 196 + (t >> 5), c = t & 31;
            AH[r * 56 + c] = z;
            AL[r * 56 + c] = z;
        }
    }
    if (half == 0) gram_pass<0, 13>(xs, gS, t, wid, lane, ahi_u32, alo_u32);
    else           gram_pass<13, 12>(xs, gS, t, wid, lane, ahi_u32, alo_u32);
}

// =====================================================================
// K2: 20 ALS iterations; S streamed from L2 (panel layout, coalesced).
// smem only 14 KB -> 2 CTAs/SM, grid 256 = single wave.
// =====================================================================
#define K2_Q    0
#define K2_QP   784
#define K2_P    2352
#define K2_B    3136
#define K2_C    3192
#define K2_BTB  3248
#define K2_CTC  3264
#define K2_ATA  3280
#define K2_GI   3296
#define K2_M    3312
#define K2_REDA 3368
#define K2_FLOATS 3592        // 14368 B

__global__ void __launch_bounds__(512, 2)
k2_als(const float* __restrict__ B0, const float* __restrict__ C0)
{
    const int b = blockIdx.x;
    const int t = threadIdx.x;

    float* Q = sm + K2_Q;
    float* Qpart = sm + K2_QP;
    float* sP = sm + K2_P;
    float* sB = sm + K2_B;
    float* sC = sm + K2_C;
    float* sBtB = sm + K2_BTB;
    float* sCtC = sm + K2_CTC;
    float* sAtA = sm + K2_ATA;
    float* sGi = sm + K2_GI;
    float* sM = sm + K2_M;
    float* redA = sm + K2_REDA;

    const float4* Sp = (const float4*)(g_Sc + (size_t)b * 38416);  // [49][196] f4

    if (t >= 400 && t < 456) sB[t - 400] = B0[b * 56 + (t - 400)];
    else if (t >= 456 && t < 512) sC[t - 456] = C0[b * 56 + (t - 456)];
    __syncthreads();

    for (int it = 0; it < 20; it++) {
        if (t < 32) {
            int which = t >> 4, e = t & 15, a = e >> 2, c2 = e & 3;
            const float* F = which ? sC : sB;
            float s = 0.f;
#pragma unroll
            for (int j = 0; j < 14; j++) s += F[j * 4 + a] * F[j * 4 + c2];
            (which ? sCtC : sBtB)[e] = s;
            __syncwarp();
            if (t < 16) inv4_warp16(sBtB, sCtC, sGi, t);
        }
        __syncthreads();
        if (t < 196) {
            int j = t / 14, k = t - (t / 14) * 14;
            float kr0 = sB[j * 4 + 0] * sC[k * 4 + 0];
            float kr1 = sB[j * 4 + 1] * sC[k * 4 + 1];
            float kr2 = sB[j * 4 + 2] * sC[k * 4 + 2];
            float kr3 = sB[j * 4 + 3] * sC[k * 4 + 3];
#pragma unroll
            for (int r = 0; r < 4; r++)
                sP[t * 4 + r] = kr0 * sGi[0 * 4 + r] + kr1 * sGi[1 * 4 + r] +
                                kr2 * sGi[2 * 4 + r] + kr3 * sGi[3 * 4 + r];
        }
        __syncthreads();
        if (it == 19) break;                // final A needs only P

        // Q = S @ P; S streamed from L2, coalesced f4 panels
        if (t < 392) {
            int p = (t < 196) ? t : (t - 196);
            const float4* Pv = (const float4*)sP;
            float a0 = 0, a1 = 0, a2 = 0, a3 = 0;
            int g0 = (t < 196) ? 0 : 24;
            int g1 = (t < 196) ? 24 : 49;
#pragma unroll 4
            for (int g = g0; g < g1; ++g) {
                float4 sv = __ldg(Sp + g * 196 + p);
                float4 p0 = Pv[g * 4 + 0];
                float4 p1 = Pv[g * 4 + 1];
                float4 p2 = Pv[g * 4 + 2];
                float4 p3 = Pv[g * 4 + 3];
                a0 += sv.x * p0.x + sv.y * p1.x + sv.z * p2.x + sv.w * p3.x;
                a1 += sv.x * p0.y + sv.y * p1.y + sv.z * p2.y + sv.w * p3.y;
                a2 += sv.x * p0.z + sv.y * p1.z + sv.z * p2.z + sv.w * p3.z;
                a3 += sv.x * p0.w + sv.y * p1.w + sv.z * p2.w + sv.w * p3.w;
            }
            int h = (t < 196) ? 0 : 1;
            Qpart[p * 8 + h * 4 + 0] = a0;
            Qpart[p * 8 + h * 4 + 1] = a1;
            Qpart[p * 8 + h * 4 + 2] = a2;
            Qpart[p * 8 + h * 4 + 3] = a3;
        }
        __syncthreads();
        if (t < 196) {
#pragma unroll
            for (int r = 0; r < 4; r++)
                Q[t * 4 + r] = Qpart[t * 8 + r] + Qpart[t * 8 + 4 + r];
        }
        __syncthreads();
        if (t < 224) {
            int e = t / 14, c = t - (t / 14) * 14;
            int s_ = e >> 2, r = e & 3;
            float v = 0.f;
            int pb = c * 14;
#pragma unroll
            for (int p = 0; p < 14; p++) v += sP[(pb + p) * 4 + s_] * Q[(pb + p) * 4 + r];
            redA[e * 14 + c] = v;
        } else if (t >= 256 && t < 312) {
            int e = t - 256; int j = e >> 2, r = e & 3;
            float v = 0.f;
#pragma unroll
            for (int k = 0; k < 14; k++) v += sC[k * 4 + r] * Q[(j * 14 + k) * 4 + r];
            sM[e] = v;
        }
        __syncthreads();
        if (t < 32) {
            if (t < 16) {
                float v = 0.f;
#pragma unroll
                for (int c = 0; c < 14; c++) v += redA[t * 14 + c];
                sAtA[t] = v;
            }
            __syncwarp();
            if (t < 16) inv4_warp16(sAtA, sCtC, sGi, t);
        }
        __syncthreads();
        if (t < 56) {
            int j = t >> 2, r = t & 3;
            sB[t] = sM[j * 4 + 0] * sGi[0 * 4 + r] + sM[j * 4 + 1] * sGi[1 * 4 + r] +
                    sM[j * 4 + 2] * sGi[2 * 4 + r] + sM[j * 4 + 3] * sGi[3 * 4 + r];
        }
        __syncthreads();
        if (t < 32) {
            if (t < 16) {
                int a = t >> 2, c2 = t & 3;
                float s = 0.f;
#pragma unroll
                for (int j = 0; j < 14; j++) s += sB[j * 4 + a] * sB[j * 4 + c2];
                sBtB[t] = s;
            }
            __syncwarp();
            if (t < 16) inv4_warp16(sAtA, sBtB, sGi, t);
        } else if (t >= 64 && t < 120) {
            int e = t - 64; int k = e >> 2, r = e & 3;
            float v = 0.f;
#pragma unroll
            for (int j = 0; j < 14; j++) v += sB[j * 4 + r] * Q[(j * 14 + k) * 4 + r];
            sM[e] = v;
        }
        __syncthreads();
        if (t < 56) {
            int k = t >> 2, r = t & 3;
            sC[t] = sM[k * 4 + 0] * sGi[0 * 4 + r] + sM[k * 4 + 1] * sGi[1 * 4 + r] +
                    sM[k * 4 + 2] * sGi[2 * 4 + r] + sM[k * 4 + 3] * sGi[3 * 4 + r];
        }
        __syncthreads();
    }

    if (t < 196)
        ((float4*)(g_P + (size_t)b * 784))[t] = *(const float4*)(sP + t * 4);
}

// =====================================================================
// K3a: A = T0@Pt (smem-staged x), rank_fc, SE -> g_gate.  2 CTAs/SM.
// (unchanged from round 9)
// =====================================================================
#define A_TC   0
#define A_PT   12800
#define A_Y2   13584
#define A_RED  14096
#define A_Z    14608
#define A_W1   14640
#define A_W2   14656
#define A_FLOATS 14660        // 58640 B

__global__ void __launch_bounds__(512, 2)
k3a_gate(const float* __restrict__ x, const float* __restrict__ w1,
         const float* __restrict__ w2, const float* __restrict__ fw1,
         const float* __restrict__ fw2)
{
    const int b = blockIdx.x;
    const int t = threadIdx.x;
    const float* xs = x + (size_t)b * 100352;

    float4* Tc4 = (float4*)(sm + A_TC);
    float* Pt = sm + A_PT;
    float* sy2 = sm + A_Y2;
    float* red = sm + A_RED;
    float* sz = sm + A_Z;
    float* sw1 = sm + A_W1;
    float* sw2 = sm + A_W2;

    if (t < 196) {
        float4 p = ((const float4*)(g_P + (size_t)b * 784))[t];
        Pt[t] = p.x; Pt[196 + t] = p.y; Pt[392 + t] = p.z; Pt[588 + t] = p.w;
    } else if (t >= 448 && t < 464) sw1[t - 448] = w1[t - 448];
    else if (t >= 464 && t < 468) sw2[t - 464] = w2[t - 464];

    const int cl = t >> 3;
    const int s = t & 7;
    __syncthreads();

    for (int ch = 0; ch < 8; ch++) {
        for (int v = t; v < 3200; v += 512) {
            int i = v / 50, c4 = v - 50 * (v / 50);
            if (c4 < 49)
                Tc4[i * 50 + c4] = *(const float4*)(xs + ch * 12544 + i * 196 + c4 * 4);
        }
        __syncthreads();
        float a0 = 0, a1 = 0, a2 = 0, a3 = 0;
        if (s < 7) {
            const float* row = sm + A_TC + cl * 200;
#pragma unroll
            for (int j = 0; j < 7; j++) {
                int q = s * 28 + j * 4;
                float4 xv = *(const float4*)(row + q);
                float4 p0 = *(const float4*)(Pt + q);
                float4 p1 = *(const float4*)(Pt + 196 + q);
                float4 p2 = *(const float4*)(Pt + 392 + q);
                float4 p3 = *(const float4*)(Pt + 588 + q);
                a0 += xv.x * p0.x + xv.y * p0.y + xv.z * p0.z + xv.w * p0.w;
                a1 += xv.x * p1.x + xv.y * p1.y + xv.z * p1.z + xv.w * p1.w;
                a2 += xv.x * p2.x + xv.y * p2.y + xv.z * p2.z + xv.w * p2.w;
                a3 += xv.x * p3.x + xv.y * p3.y + xv.z * p3.z + xv.w * p3.w;
            }
        }
#pragma unroll
        for (int m = 4; m; m >>= 1) {
            a0 += __shfl_xor_sync(0xffffffffu, a0, m);
            a1 += __shfl_xor_sync(0xffffffffu, a1, m);
            a2 += __shfl_xor_sync(0xffffffffu, a2, m);
            a3 += __shfl_xor_sync(0xffffffffu, a3, m);
        }
        if (s == 0) {
            float y2 = 0.f;
#pragma unroll
            for (int s_ = 0; s_ < 4; s_++) {
                float u = a0 * sw1[s_ * 4 + 0] + a1 * sw1[s_ * 4 + 1] +
                          a2 * sw1[s_ * 4 + 2] + a3 * sw1[s_ * 4 + 3];
                u = fmaxf(u, 0.f);
                y2 += u * sw2[s_];
            }
            sy2[ch * 64 + cl] = y2;
        }
        __syncthreads();
    }
    {
        int m = t >> 4, c = t & 15;
        const float* fr = fw1 + m * 512 + c * 32;
        const float* yy = sy2 + c * 32;
        float v = 0.f;
#pragma unroll
        for (int i2 = 0; i2 < 32; i2++) v += fr[i2] * yy[i2];
        red[m * 16 + c] = v;
    }
    __syncthreads();
    if (t < 32) {
        float v = 0.f;
#pragma unroll
        for (int c = 0; c < 16; c++) v += red[t * 16 + c];
        sz[t] = fmaxf(v, 0.f);
    }
    __syncthreads();
    {
        const float* fr = fw2 + t * 32;
        float v = 0.f;
#pragma unroll
        for (int m = 0; m < 32; m++) v += fr[m] * sz[m];
        g_gate[b * 512 + t] = 1.f / (1.f + expf(-v));
    }
}

// =====================================================================
// K3b: out = x * gate[channel]  (unchanged; 31 us at DRAM roofline)
// =====================================================================
__global__ void __launch_bounds__(256)
k3b_apply(const float* __restrict__ x, float* __restrict__ out)
{
    const float4* xi = (const float4*)x;
    float4* o = (float4*)out;
    int stride = gridDim.x * 256;
    for (int v = blockIdx.x * 256 + threadIdx.x; v < 6422528; v += stride) {
        int bb = v / 25088;
        int r = v - bb * 25088;
        int c = r / 49;
        float g = __ldg(&g_gate[bb * 512 + c]);
        float4 xv = xi[v];
        o[v] = make_float4(xv.x * g, xv.y * g, xv.z * g, xv.w * g);
    }
}

extern "C" void kernel_launch(void* const* d_in, const int* in_sizes, int n_in,
                              void* d_out, int out_size) {
    const float* x   = (const float*)d_in[0];
    // d_in[1] = A0: unused (A is overwritten before first use in the reference)
    const float* B0  = (const float*)d_in[2];
    const float* C0  = (const float*)d_in[3];
    const float* w1  = (const float*)d_in[4];
    const float* w2  = (const float*)d_in[5];
    const float* fw1 = (const float*)d_in[6];
    const float* fw2 = (const float*)d_in[7];
    float* out = (float*)d_out;

    int b = in_sizes[0] / 100352;                        // 256
    size_t sm1 = (size_t)K1_FLOATS * sizeof(float);      // 72480
    size_t sm2 = (size_t)K2_FLOATS * sizeof(float);      // 14368
    size_t sm3 = (size_t)A_FLOATS * sizeof(float);       // 58640
    static int configured = 0;
    if (!configured) {
        cudaFuncSetAttribute(k1_gram,  cudaFuncAttributeMaxDynamicSharedMemorySize, (int)sm1);
        cudaFuncSetAttribute(k2_als,   cudaFuncAttributeMaxDynamicSharedMemorySize, (int)sm2);
        cudaFuncSetAttribute(k3a_gate, cudaFuncAttributeMaxDynamicSharedMemorySize, (int)sm3);
        configured = 1;
    }
    k1_gram<<<2 * b, 512, sm1>>>(x);
    k2_als<<<b, 512, sm2>>>(B0, C0);
    k3a_gate<<<b, 512, sm3>>>(x, w1, w2, fw1, fw2);
    k3b_apply<<<2048, 256>>>(x, out);
}

// round 13
// speedup vs baseline: 1.4283x; 1.0086x over previous
#include <cuda_runtime.h>
#include <cuda_bf16.h>
#include <cstdint>
#include <math.h>

#define EPSR 1e-6f
#define NSAMP 256

// ---------------- global scratch (static; no allocation) ----------
// S in float4-panel layout: panel g (g<49) holds cols 4g..4g+3 for all 196 rows:
//   addr(p, 4g+j) = g*784 + p*4 + j   (lane-consecutive p -> coalesced f4 reads)
__device__ float g_Sc[NSAMP * 49 * 784];     // 38416 f/sample = 39.3 MB (L2-resident)
__device__ float g_P[NSAMP * 196 * 4];       // final projection (A = T0 @ P)

__device__ __forceinline__ uint32_t smem_u32(const void* p) {
    uint32_t a;
    asm("{ .reg .u64 t; cvta.to.shared.u64 t, %1; cvt.u32.u64 %0, t; }" : "=r"(a) : "l"(p));
    return a;
}

// Warp-parallel 4x4 SPD inverse via adjugate (lanes 0..15)
__device__ __forceinline__ void inv4_warp16(const float* __restrict__ ga,
                                            const float* __restrict__ gb,
                                            float* __restrict__ gi, int t)
{
    float G[16];
#pragma unroll
    for (int e = 0; e < 16; e++)
        G[e] = ga[e] * gb[e] + ((e % 5 == 0) ? EPSR : 0.f);
    int i = t >> 2, j = t & 3;
    int r0 = (i == 0) ? 1 : 0, r1 = (i < 2) ? 2 : 1, r2 = (i < 3) ? 3 : 2;
    int c0 = (j == 0) ? 1 : 0, c1 = (j < 2) ? 2 : 1, c2 = (j < 3) ? 3 : 2;
    float a = G[r0 * 4 + c0], bb = G[r0 * 4 + c1], c = G[r0 * 4 + c2];
    float d = G[r1 * 4 + c0], e  = G[r1 * 4 + c1], f = G[r1 * 4 + c2];
    float g = G[r2 * 4 + c0], h  = G[r2 * 4 + c1], i2 = G[r2 * 4 + c2];
    float det3 = a * (e * i2 - f * h) - bb * (d * i2 - f * g) + c * (d * h - e * g);
    float cof = ((i + j) & 1) ? -det3 : det3;
    const unsigned m16 = 0x0000ffffu;
    float c0v = __shfl_sync(m16, cof, 0);
    float c1v = __shfl_sync(m16, cof, 1);
    float c2v = __shfl_sync(m16, cof, 2);
    float c3v = __shfl_sync(m16, cof, 3);
    float det = G[0] * c0v + G[1] * c1v + G[2] * c2v + G[3] * c3v;
    float cji = __shfl_sync(m16, cof, j * 4 + i);
    gi[t] = cji / det;
}

#define MMA_BF16(D, A, B)                                                         \
    asm volatile("mma.sync.aligned.m16n8k16.row.col.f32.bf16.bf16.f32 "           \
        "{%0,%1,%2,%3}, {%4,%5,%6,%7}, {%8,%9}, {%0,%1,%2,%3};"                   \
        : "+f"((D)[0]), "+f"((D)[1]), "+f"((D)[2]), "+f"((D)[3])                  \
        : "r"((A)[0]), "r"((A)[1]), "r"((A)[2]), "r"((A)[3]),                     \
          "r"((B)[0]), "r"((B)[1]))

#define LDM_X4(R, ADDR)                                                           \
    asm volatile("ldmatrix.sync.aligned.m8n8.x4.shared.b16 {%0,%1,%2,%3}, [%4];"  \
        : "=r"((R)[0]), "=r"((R)[1]), "=r"((R)[2]), "=r"((R)[3]) : "r"(ADDR))

#define LDM_X2(R, ADDR)                                                           \
    asm volatile("ldmatrix.sync.aligned.m8n8.x2.shared.b16 {%0,%1}, [%2];"        \
        : "=r"((R)[0]), "=r"((R)[1]) : "r"(ADDR))

// =====================================================================
// K1: S = T0^T T0 via mma.sync (bf16 two-term split).
// Grid 2*NSAMP: CTA (b, half) computes n-tiles [0,13) or [13,25).
// 2 CTAs/SM.  Panels written straight from accumulators to g_Sc.
// =====================================================================
#define K1_STG  0
#define K1_AHI  6472
#define K1_ALO  12296
#define K1_FLOATS 18120       // 72480 B

extern __shared__ float sm[];

template<int NI0, int NT>
__device__ __forceinline__ void gram_pass(const float* __restrict__ xs,
                                          float* __restrict__ gS,
                                          int t, int wid, int lane,
                                          uint32_t ahi_u32, uint32_t alo_u32)
{
    float acc[NT][4];
#pragma unroll
    for (int i = 0; i < NT; i++) {
        acc[i][0] = 0.f; acc[i][1] = 0.f; acc[i][2] = 0.f; acc[i][3] = 0.f;
    }
    float* stgT = sm + K1_STG;
    __nv_bfloat16* AH = (__nv_bfloat16*)(sm + K1_AHI);
    __nv_bfloat16* AL = (__nv_bfloat16*)(sm + K1_ALO);
    const int mi = wid;

    for (int ch = 0; ch < 16; ++ch) {
        // stage 32 channels x 196 floats TRANSPOSED: stg_T[i][c], pitch 33
        {
            const float4* src = (const float4*)(xs + ch * 32 * 196);
            for (int v = t; v < 1568; v += 512) {
                int c = v / 49, i4 = v - 49 * c;
                float4 xv = src[v];
                float* d = stgT + (i4 * 4) * 33 + c;
                d[0]  = xv.x;
                d[33] = xv.y;
                d[66] = xv.z;
                d[99] = xv.w;
            }
        }
        __syncthreads();
        // convert to bf16 hi/lo: conflict-free row reads, contiguous stores
        for (int r = wid; r < 196; r += 16) {
            float v0 = stgT[r * 33 + lane];
            __nv_bfloat16 h = __float2bfloat16(v0);
            float hf = __bfloat162float(h);
            __nv_bfloat16 l = __float2bfloat16(v0 - hf);
            AH[r * 56 + lane] = h;
            AL[r * 56 + lane] = l;
        }
        __syncthreads();
        if (wid < 13) {
#pragma unroll
            for (int k16 = 0; k16 < 2; ++k16) {
                const int kof = k16 * 16;
                uint32_t aoff = (uint32_t)((mi * 16 + (lane & 15)) * 112 +
                                           (kof + ((lane >> 4) << 3)) * 2);
                uint32_t ah[4], al[4];
                LDM_X4(ah, ahi_u32 + aoff);
                LDM_X4(al, alo_u32 + aoff);
                uint32_t boff = (uint32_t)((lane & 7) * 112 + (kof + (lane & 8)) * 2);
#pragma unroll
                for (int nt = 0; nt < NT; ++nt) {
                    uint32_t bo = boff + (uint32_t)((NI0 + nt) * 8 * 112);
                    uint32_t bh[2], bl[2];
                    LDM_X2(bh, ahi_u32 + bo);
                    LDM_X2(bl, alo_u32 + bo);
                    MMA_BF16(acc[nt], ah, bh);
                    MMA_BF16(acc[nt], ah, bl);
                    MMA_BF16(acc[nt], al, bh);
                }
            }
        }
        __syncthreads();
    }
    // epilogue: registers -> g_Sc panels (float2 stores, 8B aligned)
    if (wid < 13) {
        int r0 = mi * 16 + (lane >> 2);
        int r1 = r0 + 8;
#pragma unroll
        for (int nt = 0; nt < NT; ++nt) {
            int cn = (NI0 + nt) * 8 + (lane & 3) * 2;   // even, < 200
            if (cn < 196) {
                int base = (cn >> 2) * 784 + (cn & 3);
                if (r0 < 196) *(float2*)(gS + base + r0 * 4) = make_float2(acc[nt][0], acc[nt][1]);
                if (r1 < 196) *(float2*)(gS + base + r1 * 4) = make_float2(acc[nt][2], acc[nt][3]);
            }
        }
    }
}

__global__ void __launch_bounds__(512, 2)
k1_gram(const float* __restrict__ x)
{
    const int b = blockIdx.x >> 1;
    const int half = blockIdx.x & 1;
    const int t = threadIdx.x;
    const int wid = t >> 5, lane = t & 31;
    const float* xs = x + (size_t)b * 100352;
    float* gS = g_Sc + (size_t)b * 38416;

    const uint32_t ahi_u32 = smem_u32(sm + K1_AHI);
    const uint32_t alo_u32 = smem_u32(sm + K1_ALO);

    // zero pad rows 196..207 (cols 0..31) of AHI/ALO
    {
        __nv_bfloat16* AH = (__nv_bfloat16*)(sm + K1_AHI);
        __nv_bfloat16* AL = (__nv_bfloat16*)(sm + K1_ALO);
        __nv_bfloat16 z = __float2bfloat16(0.f);
        if (t < 384) {
            int r = 196 + (t >> 5), c = t & 31;
            AH[r * 56 + c] = z;
            AL[r * 56 + c] = z;
        }
    }
    if (half == 0) gram_pass<0, 13>(xs, gS, t, wid, lane, ahi_u32, alo_u32);
    else           gram_pass<13, 12>(xs, gS, t, wid, lane, ahi_u32, alo_u32);
}

// =====================================================================
// K2: 20 ALS iterations; S streamed from L2 (panel layout, coalesced).
// smem 14 KB -> 2 CTAs/SM, grid 256 = single wave.  Q loop unroll 8.
// =====================================================================
#define K2_Q    0
#define K2_QP   784
#define K2_P    2352
#define K2_B    3136
#define K2_C    3192
#define K2_BTB  3248
#define K2_CTC  3264
#define K2_ATA  3280
#define K2_GI   3296
#define K2_M    3312
#define K2_REDA 3368
#define K2_FLOATS 3592        // 14368 B

__global__ void __launch_bounds__(512, 2)
k2_als(const float* __restrict__ B0, const float* __restrict__ C0)
{
    const int b = blockIdx.x;
    const int t = threadIdx.x;

    float* Q = sm + K2_Q;
    float* Qpart = sm + K2_QP;
    float* sP = sm + K2_P;
    float* sB = sm + K2_B;
    float* sC = sm + K2_C;
    float* sBtB = sm + K2_BTB;
    float* sCtC = sm + K2_CTC;
    float* sAtA = sm + K2_ATA;
    float* sGi = sm + K2_GI;
    float* sM = sm + K2_M;
    float* redA = sm + K2_REDA;

    const float4* Sp = (const float4*)(g_Sc + (size_t)b * 38416);  // [49][196] f4

    if (t >= 400 && t < 456) sB[t - 400] = B0[b * 56 + (t - 400)];
    else if (t >= 456 && t < 512) sC[t - 456] = C0[b * 56 + (t - 456)];
    __syncthreads();

    for (int it = 0; it < 20; it++) {
        if (t < 32) {
            int which = t >> 4, e = t & 15, a = e >> 2, c2 = e & 3;
            const float* F = which ? sC : sB;
            float s = 0.f;
#pragma unroll
            for (int j = 0; j < 14; j++) s += F[j * 4 + a] * F[j * 4 + c2];
            (which ? sCtC : sBtB)[e] = s;
            __syncwarp();
            if (t < 16) inv4_warp16(sBtB, sCtC, sGi, t);
        }
        __syncthreads();
        if (t < 196) {
            int j = t / 14, k = t - (t / 14) * 14;
            float kr0 = sB[j * 4 + 0] * sC[k * 4 + 0];
            float kr1 = sB[j * 4 + 1] * sC[k * 4 + 1];
            float kr2 = sB[j * 4 + 2] * sC[k * 4 + 2];
            float kr3 = sB[j * 4 + 3] * sC[k * 4 + 3];
#pragma unroll
            for (int r = 0; r < 4; r++)
                sP[t * 4 + r] = kr0 * sGi[0 * 4 + r] + kr1 * sGi[1 * 4 + r] +
                                kr2 * sGi[2 * 4 + r] + kr3 * sGi[3 * 4 + r];
        }
        __syncthreads();
        if (it == 19) break;                // final A needs only P

        // Q = S @ P; S streamed from L2, coalesced f4 panels, deep MLP
        if (t < 392) {
            int p = (t < 196) ? t : (t - 196);
            const float4* Pv = (const float4*)sP;
            float a0 = 0, a1 = 0, a2 = 0, a3 = 0;
            int g0 = (t < 196) ? 0 : 24;
            int g1 = (t < 196) ? 24 : 49;
#pragma unroll 8
            for (int g = g0; g < g1; ++g) {
                float4 sv = __ldg(Sp + g * 196 + p);
                float4 p0 = Pv[g * 4 + 0];
                float4 p1 = Pv[g * 4 + 1];
                float4 p2 = Pv[g * 4 + 2];
                float4 p3 = Pv[g * 4 + 3];
                a0 += sv.x * p0.x + sv.y * p1.x + sv.z * p2.x + sv.w * p3.x;
                a1 += sv.x * p0.y + sv.y * p1.y + sv.z * p2.y + sv.w * p3.y;
                a2 += sv.x * p0.z + sv.y * p1.z + sv.z * p2.z + sv.w * p3.z;
                a3 += sv.x * p0.w + sv.y * p1.w + sv.z * p2.w + sv.w * p3.w;
            }
            int h = (t < 196) ? 0 : 1;
            Qpart[p * 8 + h * 4 + 0] = a0;
            Qpart[p * 8 + h * 4 + 1] = a1;
            Qpart[p * 8 + h * 4 + 2] = a2;
            Qpart[p * 8 + h * 4 + 3] = a3;
        }
        __syncthreads();
        if (t < 196) {
#pragma unroll
            for (int r = 0; r < 4; r++)
                Q[t * 4 + r] = Qpart[t * 8 + r] + Qpart[t * 8 + 4 + r];
        }
        __syncthreads();
        if (t < 224) {
            int e = t / 14, c = t - (t / 14) * 14;
            int s_ = e >> 2, r = e & 3;
            float v = 0.f;
            int pb = c * 14;
#pragma unroll
            for (int p = 0; p < 14; p++) v += sP[(pb + p) * 4 + s_] * Q[(pb + p) * 4 + r];
            redA[e * 14 + c] = v;
        } else if (t >= 256 && t < 312) {
            int e = t - 256; int j = e >> 2, r = e & 3;
            float v = 0.f;
#pragma unroll
            for (int k = 0; k < 14; k++) v += sC[k * 4 + r] * Q[(j * 14 + k) * 4 + r];
            sM[e] = v;
        }
        __syncthreads();
        if (t < 32) {
            if (t < 16) {
                float v = 0.f;
#pragma unroll
                for (int c = 0; c < 14; c++) v += redA[t * 14 + c];
                sAtA[t] = v;
            }
            __syncwarp();
            if (t < 16) inv4_warp16(sAtA, sCtC, sGi, t);
        }
        __syncthreads();
        if (t < 56) {
            int j = t >> 2, r = t & 3;
            sB[t] = sM[j * 4 + 0] * sGi[0 * 4 + r] + sM[j * 4 + 1] * sGi[1 * 4 + r] +
                    sM[j * 4 + 2] * sGi[2 * 4 + r] + sM[j * 4 + 3] * sGi[3 * 4 + r];
        }
        __syncthreads();
        if (t < 32) {
            if (t < 16) {
                int a = t >> 2, c2 = t & 3;
                float s = 0.f;
#pragma unroll
                for (int j = 0; j < 14; j++) s += sB[j * 4 + a] * sB[j * 4 + c2];
                sBtB[t] = s;
            }
            __syncwarp();
            if (t < 16) inv4_warp16(sAtA, sBtB, sGi, t);
        } else if (t >= 64 && t < 120) {
            int e = t - 64; int k = e >> 2, r = e & 3;
            float v = 0.f;
#pragma unroll
            for (int j = 0; j < 14; j++) v += sB[j * 4 + r] * Q[(j * 14 + k) * 4 + r];
            sM[e] = v;
        }
        __syncthreads();
        if (t < 56) {
            int k = t >> 2, r = t & 3;
            sC[t] = sM[k * 4 + 0] * sGi[0 * 4 + r] + sM[k * 4 + 1] * sGi[1 * 4 + r] +
                    sM[k * 4 + 2] * sGi[2 * 4 + r] + sM[k * 4 + 3] * sGi[3 * 4 + r];
        }
        __syncthreads();
    }

    if (t < 196)
        ((float4*)(g_P + (size_t)b * 784))[t] = *(const float4*)(sP + t * 4);
}

// =====================================================================
// K3: A = T0@Pt (smem-staged x), rank_fc, SE gate, APPLY (merged k3a+k3b).
// 2 CTAs/SM, single wave.  x re-read for apply hits L2 (just staged).
// =====================================================================
#define A_TC   0              // staging [64][50] f4 = 12800 floats
#define A_PT   12800          // Pt [4][196] = 784
#define A_Y2   13584
#define A_RED  14096
#define A_Z    14608
#define A_W1   14640
#define A_W2   14656
#define A_G    14660          // gate [512]
#define A_FLOATS 15172        // 60688 B

__global__ void __launch_bounds__(512, 2)
k3_gate_apply(const float* __restrict__ x, const float* __restrict__ w1,
              const float* __restrict__ w2, const float* __restrict__ fw1,
              const float* __restrict__ fw2, float* __restrict__ out)
{
    const int b = blockIdx.x;
    const int t = threadIdx.x;
    const int wid = t >> 5, lane = t & 31;
    const float* xs = x + (size_t)b * 100352;

    float4* Tc4 = (float4*)(sm + A_TC);
    float* Pt = sm + A_PT;
    float* sy2 = sm + A_Y2;
    float* red = sm + A_RED;
    float* sz = sm + A_Z;
    float* sw1 = sm + A_W1;
    float* sw2 = sm + A_W2;
    float* sg = sm + A_G;

    if (t < 196) {
        float4 p = ((const float4*)(g_P + (size_t)b * 784))[t];
        Pt[t] = p.x; Pt[196 + t] = p.y; Pt[392 + t] = p.z; Pt[588 + t] = p.w;
    } else if (t >= 448 && t < 464) sw1[t - 448] = w1[t - 448];
    else if (t >= 464 && t < 468) sw2[t - 464] = w2[t - 464];

    const int cl = t >> 3;                  // channel-within-chunk 0..63
    const int s = t & 7;                    // col-slice (7 active)
    __syncthreads();

    for (int ch = 0; ch < 8; ch++) {
        for (int v = t; v < 3200; v += 512) {
            int i = v / 50, c4 = v - 50 * (v / 50);
            if (c4 < 49)
                Tc4[i * 50 + c4] = *(const float4*)(xs + ch * 12544 + i * 196 + c4 * 4);
        }
        __syncthreads();
        float a0 = 0, a1 = 0, a2 = 0, a3 = 0;
        if (s < 7) {
            const float* row = sm + A_TC + cl * 200;
#pragma unroll
            for (int j = 0; j < 7; j++) {
                int q = s * 28 + j * 4;
                float4 xv = *(const float4*)(row + q);
                float4 p0 = *(const float4*)(Pt + q);
                float4 p1 = *(const float4*)(Pt + 196 + q);
                float4 p2 = *(const float4*)(Pt + 392 + q);
                float4 p3 = *(const float4*)(Pt + 588 + q);
                a0 += xv.x * p0.x + xv.y * p0.y + xv.z * p0.z + xv.w * p0.w;
                a1 += xv.x * p1.x + xv.y * p1.y + xv.z * p1.z + xv.w * p1.w;
                a2 += xv.x * p2.x + xv.y * p2.y + xv.z * p2.z + xv.w * p2.w;
                a3 += xv.x * p3.x + xv.y * p3.y + xv.z * p3.z + xv.w * p3.w;
            }
        }
#pragma unroll
        for (int m = 4; m; m >>= 1) {
            a0 += __shfl_xor_sync(0xffffffffu, a0, m);
            a1 += __shfl_xor_sync(0xffffffffu, a1, m);
            a2 += __shfl_xor_sync(0xffffffffu, a2, m);
            a3 += __shfl_xor_sync(0xffffffffu, a3, m);
        }
        if (s == 0) {
            float y2 = 0.f;
#pragma unroll
            for (int s_ = 0; s_ < 4; s_++) {
                float u = a0 * sw1[s_ * 4 + 0] + a1 * sw1[s_ * 4 + 1] +
                          a2 * sw1[s_ * 4 + 2] + a3 * sw1[s_ * 4 + 3];
                u = fmaxf(u, 0.f);
                y2 += u * sw2[s_];
            }
            sy2[ch * 64 + cl] = y2;
        }
        __syncthreads();
    }
    // z = relu(fw1 @ y2)
    {
        int m = t >> 4, c = t & 15;
        const float* fr = fw1 + m * 512 + c * 32;
        const float* yy = sy2 + c * 32;
        float v = 0.f;
#pragma unroll
        for (int i2 = 0; i2 < 32; i2++) v += fr[i2] * yy[i2];
        red[m * 16 + c] = v;
    }
    __syncthreads();
    if (t < 32) {
        float v = 0.f;
#pragma unroll
        for (int c = 0; c < 16; c++) v += red[t * 16 + c];
        sz[t] = fmaxf(v, 0.f);
    }
    __syncthreads();
    {
        const float* fr = fw2 + t * 32;
        float v = 0.f;
#pragma unroll
        for (int m = 0; m < 32; m++) v += fr[m] * sz[m];
        sg[t] = 1.f / (1.f + expf(-v));
    }
    __syncthreads();
    // apply gate: out = x * g[channel]; x re-read from L2 (just staged)
    {
        const float4* xin4 = (const float4*)xs;
        float4* out4 = (float4*)(out + (size_t)b * 100352);
        for (int c = wid; c < 512; c += 16) {
            float g = sg[c];
            const float4* xr = xin4 + c * 49;
            float4* orow = out4 + c * 49;
            float4 xv = xr[lane];
            if (lane < 17) {
                float4 xv2 = xr[lane + 32];
                orow[lane + 32] = make_float4(xv2.x * g, xv2.y * g, xv2.z * g, xv2.w * g);
            }
            orow[lane] = make_float4(xv.x * g, xv.y * g, xv.z * g, xv.w * g);
        }
    }
}

extern "C" void kernel_launch(void* const* d_in, const int* in_sizes, int n_in,
                              void* d_out, int out_size) {
    const float* x   = (const float*)d_in[0];
    // d_in[1] = A0: unused (A is overwritten before first use in the reference)
    const float* B0  = (const float*)d_in[2];
    const float* C0  = (const float*)d_in[3];
    const float* w1  = (const float*)d_in[4];
    const float* w2  = (const float*)d_in[5];
    const float* fw1 = (const float*)d_in[6];
    const float* fw2 = (const float*)d_in[7];
    float* out = (float*)d_out;

    int b = in_sizes[0] / 100352;                        // 256
    size_t sm1 = (size_t)K1_FLOATS * sizeof(float);      // 72480
    size_t sm2 = (size_t)K2_FLOATS * sizeof(float);      // 14368
    size_t sm3 = (size_t)A_FLOATS * sizeof(float);       // 60688
    static int configured = 0;
    if (!configured) {
        cudaFuncSetAttribute(k1_gram,       cudaFuncAttributeMaxDynamicSharedMemorySize, (int)sm1);
        cudaFuncSetAttribute(k2_als,        cudaFuncAttributeMaxDynamicSharedMemorySize, (int)sm2);
        cudaFuncSetAttribute(k3_gate_apply, cudaFuncAttributeMaxDynamicSharedMemorySize, (int)sm3);
        configured = 1;
    }
    k1_gram<<<2 * b, 512, sm1>>>(x);
    k2_als<<<b, 512, sm2>>>(B0, C0);
    k3_gate_apply<<<b, 512, sm3>>>(x, w1, w2, fw1, fw2, out);
}